// round 9
// baseline (speedup 1.0000x reference)
#include <cuda_runtime.h>
#include <cuda_bf16.h>

// Fused DCNv2 forward, 2 pixels/thread, packed f32x2 math, constant-memory
// weights (uniform LDCU path), and an NHWC4 re-layout of x so every bilinear
// corner / conv-window position is ONE LDG.128 covering all 3 channels.

#define HH 512
#define WW 512
#define CC 3
#define OCC 27
#define KK 9
#define HW (HH * WW)

typedef unsigned long long u64;

struct WConst {
    u64   wd[OCC * 27];   // duplicated {w,w}, transposed: wd[g*27+oc], g=c*9+ky*3+kx
    u64   wdd[3 * 27];    // duplicated w_def [o*27 + c*9 + k]
    float boff[28];
    float bdef[4];
};

__constant__ WConst c_w;
__device__   WConst g_scratch;

// x re-laid out as (B, H, W, 4): xyz = channels 0..2, w = 0.  32 MB static scratch.
__device__ __align__(16) float4 g_xhwc[8 * HW];

__device__ __forceinline__ u64 pk2(float lo, float hi) {
    u64 r; asm("mov.b64 %0, {%1, %2};" : "=l"(r) : "f"(lo), "f"(hi)); return r;
}
__device__ __forceinline__ void upk2(u64 v, float& lo, float& hi) {
    asm("mov.b64 {%0, %1}, %2;" : "=f"(lo), "=f"(hi) : "l"(v));
}
__device__ __forceinline__ void ffma2(u64& acc, u64 a, u64 b) {
    asm("fma.rn.f32x2 %0, %1, %2, %0;" : "+l"(acc) : "l"(a), "l"(b));
}
__device__ __forceinline__ float f4c(const float4& q, int c) {
    return (c == 0) ? q.x : (c == 1) ? q.y : q.z;
}

__global__ void dcn_prep_kernel(const float* __restrict__ w_off,
                                const float* __restrict__ b_off,
                                const float* __restrict__ w_def,
                                const float* __restrict__ b_def)
{
    const int i = threadIdx.x;
    if (i < OCC * 27) {
        const int g = i / OCC, oc = i % OCC;
        const float w = w_off[oc * 27 + g];
        g_scratch.wd[g * 27 + oc] = pk2(w, w);
    } else if (i < OCC * 27 + 81) {
        const int j = i - OCC * 27;
        const float w = w_def[j];
        g_scratch.wdd[j] = pk2(w, w);
    } else if (i < OCC * 27 + 81 + 28) {
        const int j = i - (OCC * 27 + 81);
        g_scratch.boff[j] = (j < OCC) ? b_off[j] : 0.0f;
    } else if (i < OCC * 27 + 81 + 32) {
        const int j = i - (OCC * 27 + 81 + 28);
        g_scratch.bdef[j] = (j < 3) ? b_def[j] : 0.0f;
    }
}

__global__ __launch_bounds__(256)
void dcn_hwc_kernel(const float* __restrict__ x)
{
    const int i = blockIdx.x * blockDim.x + threadIdx.x;   // 0 .. 8*HW-1
    const int hw = i & (HW - 1);
    const int b  = i >> 18;
    const float* xb = x + (size_t)b * CC * HW;
    g_xhwc[i] = make_float4(__ldg(xb + hw), __ldg(xb + HW + hw),
                            __ldg(xb + 2 * HW + hw), 0.0f);
}

__global__ __launch_bounds__(128, 6)
void dcn_fused_hwc(float* __restrict__ out)
{
    // One thread = pixel pair (hI, wI), (hI, wI+1) with wI even.
    const int idx = blockIdx.x * blockDim.x + threadIdx.x;   // 0 .. 8*512*256-1
    const int wI = (idx & 255) << 1;
    const int hI = (idx >> 8) & (HH - 1);
    const int b  = idx >> 17;

    const float4* xb4 = g_xhwc + (size_t)b * HW;
    const float4 zero4 = make_float4(0.0f, 0.0f, 0.0f, 0.0f);

    // ---- offset/mask conv, row-streamed (one 4-wide float4 row live) ----
    u64 ow[OCC];
#pragma unroll
    for (int oc = 0; oc < OCC; ++oc) {
        const float bv = c_w.boff[oc];
        ow[oc] = pk2(bv, bv);
    }

#pragma unroll
    for (int r = 0; r < 3; ++r) {
        const int y = hI + r - 1;
        const bool yv = ((unsigned)y < (unsigned)HH);
        float4 row[4];
#pragma unroll
        for (int j = 0; j < 4; ++j) {
            const int xx = wI + j - 1;
            const bool v = yv && ((unsigned)xx < (unsigned)WW);
            row[j] = v ? __ldg(&xb4[y * WW + xx]) : zero4;
        }
#pragma unroll
        for (int kx = 0; kx < 3; ++kx) {
#pragma unroll
            for (int c = 0; c < CC; ++c) {
                const u64 v2 = pk2(f4c(row[kx], c), f4c(row[kx + 1], c));
                const int gbase = (c * 9 + r * 3 + kx) * 27;   // compile-time
#pragma unroll
                for (int oc = 0; oc < OCC; ++oc)
                    ffma2(ow[oc], c_w.wd[gbase + oc], v2);
            }
        }
    }

    // ---- deformable sampling + channel mix (packed across the 2 pixels) ----
    u64 acc[3];
#pragma unroll
    for (int o = 0; o < 3; ++o) {
        const float bv = c_w.bdef[o];
        acc[o] = pk2(bv, bv);
    }

#pragma unroll
    for (int k = 0; k < KK; ++k) {
        float oy0, oy1, ox0, ox1, z0, z1;
        upk2(ow[2 * k],     oy0, oy1);
        upk2(ow[2 * k + 1], ox0, ox1);
        upk2(ow[18 + k],    z0,  z1);
        const float m0 = __fdividef(1.0f, 1.0f + __expf(-z0));
        const float m1 = __fdividef(1.0f, 1.0f + __expf(-z1));

        const float kyf = (float)(k / 3 - 1);
        const float kxf = (float)(k % 3 - 1);

        float val[2][CC];
#pragma unroll
        for (int p = 0; p < 2; ++p) {
            const float py = (float)hI + kyf + (p ? oy1 : oy0);
            const float px = (float)(wI + p) + kxf + (p ? ox1 : ox0);
            const float y0f = floorf(py);
            const float x0f = floorf(px);
            const float dy = py - y0f;
            const float dx = px - x0f;
            const int y0 = (int)y0f;
            const int x0 = (int)x0f;

            const float w00 = (1.0f - dy) * (1.0f - dx);
            const float w01 = (1.0f - dy) * dx;
            const float w10 = dy * (1.0f - dx);
            const float w11 = dy * dx;

            const bool y0v = ((unsigned)y0       < (unsigned)HH);
            const bool y1v = ((unsigned)(y0 + 1) < (unsigned)HH);
            const bool x0v = ((unsigned)x0       < (unsigned)WW);
            const bool x1v = ((unsigned)(x0 + 1) < (unsigned)WW);
            const int i00 = y0 * WW + x0;

            const float4 q00 = (y0v && x0v) ? __ldg(&xb4[i00])          : zero4;
            const float4 q01 = (y0v && x1v) ? __ldg(&xb4[i00 + 1])      : zero4;
            const float4 q10 = (y1v && x0v) ? __ldg(&xb4[i00 + WW])     : zero4;
            const float4 q11 = (y1v && x1v) ? __ldg(&xb4[i00 + WW + 1]) : zero4;

#pragma unroll
            for (int c = 0; c < CC; ++c)
                val[p][c] = f4c(q00, c) * w00 + f4c(q01, c) * w01
                          + f4c(q10, c) * w10 + f4c(q11, c) * w11;
        }

#pragma unroll
        for (int c = 0; c < CC; ++c) {
            const u64 vp = pk2(val[0][c] * m0, val[1][c] * m1);
#pragma unroll
            for (int o = 0; o < 3; ++o)
                ffma2(acc[o], c_w.wdd[o * 27 + c * 9 + k], vp);
        }
    }

    const size_t obase = (size_t)b * 3 * HW + (size_t)hI * WW + wI;
#pragma unroll
    for (int o = 0; o < 3; ++o) {
        float lo, hi; upk2(acc[o], lo, hi);
        *reinterpret_cast<float2*>(out + obase + (size_t)o * HW) = make_float2(lo, hi);
    }
}

extern "C" void kernel_launch(void* const* d_in, const int* in_sizes, int n_in,
                              void* d_out, int out_size)
{
    const float* x     = (const float*)d_in[0];
    const float* w_off = (const float*)d_in[1];
    const float* b_off = (const float*)d_in[2];
    const float* w_def = (const float*)d_in[3];
    const float* b_def = (const float*)d_in[4];
    float* out = (float*)d_out;

    // 1) Build weight blob + biases in device scratch.
    dcn_prep_kernel<<<1, 896>>>(w_off, b_off, w_def, b_def);

    // 2) Stage blob into __constant__ (one D2D copy).
    void* scratch_ptr = nullptr;
    cudaGetSymbolAddress(&scratch_ptr, g_scratch);
    cudaMemcpyToSymbolAsync(c_w, scratch_ptr, sizeof(WConst), 0,
                            cudaMemcpyDeviceToDevice);

    // 3) Re-layout x to NHWC4.
    dcn_hwc_kernel<<<(8 * HW) / 256, 256>>>(x);

    // 4) Main fused kernel.
    const int totalPairs = 8 * 512 * 256;    // 1,048,576 pixel pairs
    dcn_fused_hwc<<<totalPairs / 128, 128>>>(out);
}